// round 3
// baseline (speedup 1.0000x reference)
#include <cuda_runtime.h>
#include <math.h>

#define BB   32
#define LL   128
#define HH   200
#define NPW  20
#define NCOL 105
#define EPSV 1e-8f
#define OUTH (BB*LL*NCOL)

// ---------------- scratch (device globals; no allocation allowed) ----------
__device__ float g_cpm[BB*LL*HH];
__device__ float g_chm[BB*LL*HH];
__device__ float g_norm_p[BB*LL];
__device__ float g_norm_h[BB*LL];
__device__ float g_np_p[BB*LL*NPW];
__device__ float g_np_h[BB*LL*NPW];
__device__ float g_cos[BB*LL*LL];
__device__ float g_rowsum[BB*LL];
__device__ float g_colsum[BB*LL];
__device__ float g_amean_h[BB*LL*HH];
__device__ float g_amax_h[BB*LL*HH];
__device__ float g_amean_p[BB*LL*HH];
__device__ float g_amax_p[BB*LL*HH];
__device__ float g_len_p[BB], g_len_h[BB];
__device__ int   g_idx_p[BB], g_idx_h[BB];

// ---------------- helpers ----------------
__device__ __forceinline__ float wredsum(float v) {
#pragma unroll
    for (int o = 16; o > 0; o >>= 1) v += __shfl_xor_sync(0xffffffffu, v, o);
    return v;
}
__device__ __forceinline__ void wred3(float& a, float& b, float& c) {
#pragma unroll
    for (int o = 16; o > 0; o >>= 1) {
        a += __shfl_xor_sync(0xffffffffu, a, o);
        b += __shfl_xor_sync(0xffffffffu, b, o);
        c += __shfl_xor_sync(0xffffffffu, c, o);
    }
}

// ---------------- lens: mask sums + last-token index ----------------
__global__ void lens_kernel(const float* __restrict__ mask_p,
                            const float* __restrict__ mask_h) {
    int t = threadIdx.x;
    if (t < BB) {
        float s = 0.f;
        for (int i = 0; i < LL; i++) s += mask_p[t*LL + i];
        g_len_p[t] = s;
        int id = (int)(s + 0.5f) - 1;
        g_idx_p[t] = id < 0 ? 0 : id;
    } else if (t < 2*BB) {
        int b = t - BB;
        float s = 0.f;
        for (int i = 0; i < LL; i++) s += mask_h[b*LL + i];
        g_len_h[b] = s;
        int id = (int)(s + 0.5f) - 1;
        g_idx_h[b] = id < 0 ? 0 : id;
    }
}

// ---------------- preprocess: masked context, norms, maxpool weighted norms --
__global__ void prep_kernel(const float* __restrict__ ctx_p, const float* __restrict__ mask_p,
                            const float* __restrict__ ctx_h, const float* __restrict__ mask_h,
                            const float* __restrict__ w_mp) {
    int side = blockIdx.y;
    const float* ctx  = side ? ctx_h  : ctx_p;
    const float* mask = side ? mask_h : mask_p;
    float* xm  = side ? g_chm    : g_cpm;
    float* nrm = side ? g_norm_h : g_norm_p;
    float* npl = side ? g_np_h   : g_np_p;

    int warp = (blockIdx.x * blockDim.x + threadIdx.x) >> 5;
    int lane = threadIdx.x & 31;
    if (warp >= BB*LL) return;

    float m = mask[warp];
    const float* x = ctx + warp*HH;
    float v[7];
#pragma unroll
    for (int i = 0; i < 7; i++) {
        int h = lane + 32*i;
        float val = (h < HH) ? x[h]*m : 0.f;
        v[i] = val;
        if (h < HH) xm[warp*HH + h] = val;
    }
    float s = 0.f;
#pragma unroll
    for (int i = 0; i < 7; i++) s += v[i]*v[i];
    s = wredsum(s);
    if (lane == 0) nrm[warp] = sqrtf(s);

    for (int k = 0; k < NPW; k++) {
        float a = 0.f;
#pragma unroll
        for (int i = 0; i < 7; i++) {
            int h = lane + 32*i;
            if (h < HH) { float w = w_mp[k*HH + h]; a += w*w*v[i]*v[i]; }
        }
        a = wredsum(a);
        if (lane == 0) npl[warp*NPW + k] = sqrtf(a);
    }
}

// ---------------- cos matrix GEMM + row/col reductions ----------------
// One block per b: 128x128x200, 256 threads, 8x8 microtile.
__global__ __launch_bounds__(256) void cos_kernel(const float* __restrict__ mask_p,
                                                  const float* __restrict__ mask_h,
                                                  float* __restrict__ out) {
    __shared__ __align__(16) float As[8][128];
    __shared__ __align__(16) float Bs[8][128];
    __shared__ float red[128][16];
    __shared__ float mp_s[128], mh_s[128];

    int b  = blockIdx.x;
    int t  = threadIdx.x;
    int tx = t & 15, ty = t >> 4;
    if (t < 128) { mp_s[t] = mask_p[b*LL + t]; mh_s[t] = mask_h[b*LL + t]; }

    float acc[8][8];
#pragma unroll
    for (int i = 0; i < 8; i++)
#pragma unroll
        for (int j = 0; j < 8; j++) acc[i][j] = 0.f;

    const float* A  = g_cpm + b*LL*HH;
    const float* Bm = g_chm + b*LL*HH;
    int lrow = t >> 1, lpart = t & 1;

    for (int h0 = 0; h0 < HH; h0 += 8) {
        float4 a4 = *(const float4*)(A  + lrow*HH + h0 + lpart*4);
        float4 b4 = *(const float4*)(Bm + lrow*HH + h0 + lpart*4);
        __syncthreads();
        As[lpart*4+0][lrow] = a4.x; As[lpart*4+1][lrow] = a4.y;
        As[lpart*4+2][lrow] = a4.z; As[lpart*4+3][lrow] = a4.w;
        Bs[lpart*4+0][lrow] = b4.x; Bs[lpart*4+1][lrow] = b4.y;
        Bs[lpart*4+2][lrow] = b4.z; Bs[lpart*4+3][lrow] = b4.w;
        __syncthreads();
#pragma unroll
        for (int kk = 0; kk < 8; kk++) {
            float4 a0 = *(const float4*)&As[kk][ty*8];
            float4 a1 = *(const float4*)&As[kk][ty*8+4];
            float4 b0 = *(const float4*)&Bs[kk][tx*8];
            float4 b1 = *(const float4*)&Bs[kk][tx*8+4];
            float av[8] = {a0.x,a0.y,a0.z,a0.w,a1.x,a1.y,a1.z,a1.w};
            float bv[8] = {b0.x,b0.y,b0.z,b0.w,b1.x,b1.y,b1.z,b1.w};
#pragma unroll
            for (int i = 0; i < 8; i++)
#pragma unroll
                for (int j = 0; j < 8; j++) acc[i][j] += av[i]*bv[j];
        }
    }
    __syncthreads();

    float npv[8], nhv[8];
#pragma unroll
    for (int i = 0; i < 8; i++) npv[i] = g_norm_p[b*LL + ty*8 + i];
#pragma unroll
    for (int j = 0; j < 8; j++) nhv[j] = g_norm_h[b*LL + tx*8 + j];

    float* cosb = g_cos + b*LL*LL;
    float rsum[8], rmax[8], csum[8], cmax[8];
#pragma unroll
    for (int i = 0; i < 8; i++) { rsum[i] = 0.f; rmax[i] = -3.0e38f; }
#pragma unroll
    for (int j = 0; j < 8; j++) { csum[j] = 0.f; cmax[j] = -3.0e38f; }

#pragma unroll
    for (int i = 0; i < 8; i++) {
        int p = ty*8 + i;
        float mp = mp_s[p];
#pragma unroll
        for (int j = 0; j < 8; j++) {
            int q = tx*8 + j;
            float v = acc[i][j] / fmaxf(npv[i]*nhv[j], EPSV);
            cosb[p*LL + q] = v;
            rsum[i] += v; csum[j] += v;
            if (mh_s[q] > 0.f) rmax[i] = fmaxf(rmax[i], v);
            if (mp       > 0.f) cmax[j] = fmaxf(cmax[j], v);
        }
    }
    float lenp = g_len_p[b], lenh = g_len_h[b];

#pragma unroll
    for (int i = 0; i < 8; i++) red[ty*8+i][tx] = rsum[i];
    __syncthreads();
    if (t < 128) {
        float s = 0.f;
        for (int x = 0; x < 16; x++) s += red[t][x];
        g_rowsum[b*LL + t] = s;
        out[(b*LL + t)*NCOL + 1] = (mp_s[t] > 0.f) ? s/lenh : 0.f;
    }
    __syncthreads();
#pragma unroll
    for (int i = 0; i < 8; i++) red[ty*8+i][tx] = rmax[i];
    __syncthreads();
    if (t < 128) {
        float m = -3.0e38f;
        for (int x = 0; x < 16; x++) m = fmaxf(m, red[t][x]);
        out[(b*LL + t)*NCOL + 0] = (mp_s[t] > 0.f) ? m : 0.f;
    }
    __syncthreads();
#pragma unroll
    for (int j = 0; j < 8; j++) red[tx*8+j][ty] = csum[j];
    __syncthreads();
    if (t < 128) {
        float s = 0.f;
        for (int y = 0; y < 16; y++) s += red[t][y];
        g_colsum[b*LL + t] = s;
        out[OUTH + (b*LL + t)*NCOL + 1] = (mh_s[t] > 0.f) ? s/lenp : 0.f;
    }
    __syncthreads();
#pragma unroll
    for (int j = 0; j < 8; j++) red[tx*8+j][ty] = cmax[j];
    __syncthreads();
    if (t < 128) {
        float m = -3.0e38f;
        for (int y = 0; y < 16; y++) m = fmaxf(m, red[t][y]);
        out[OUTH + (b*LL + t)*NCOL + 0] = (mh_s[t] > 0.f) ? m : 0.f;
    }
}

// ---------------- maxpool match: per (b,k) fused GEMM + max/mean epilogue ---
__global__ __launch_bounds__(256) void maxpool_kernel(const float* __restrict__ w_mp,
                                                      const float* __restrict__ mask_p,
                                                      const float* __restrict__ mask_h,
                                                      float* __restrict__ out) {
    __shared__ __align__(16) float As[8][128];
    __shared__ __align__(16) float Bs[8][128];
    __shared__ float red[128][16];
    __shared__ float mp_s[128], mh_s[128];

    int b = blockIdx.x / NPW;
    int k = blockIdx.x % NPW;
    int t = threadIdx.x;
    int tx = t & 15, ty = t >> 4;
    if (t < 128) { mp_s[t] = mask_p[b*LL + t]; mh_s[t] = mask_h[b*LL + t]; }

    float acc[8][8];
#pragma unroll
    for (int i = 0; i < 8; i++)
#pragma unroll
        for (int j = 0; j < 8; j++) acc[i][j] = 0.f;

    const float* A  = g_cpm + b*LL*HH;
    const float* Bm = g_chm + b*LL*HH;
    const float* wk = w_mp + k*HH;
    int lrow = t >> 1, lpart = t & 1;

    for (int h0 = 0; h0 < HH; h0 += 8) {
        float4 a4 = *(const float4*)(A  + lrow*HH + h0 + lpart*4);
        float4 b4 = *(const float4*)(Bm + lrow*HH + h0 + lpart*4);
        float4 w4 = *(const float4*)(wk + h0 + lpart*4);
        a4.x *= w4.x*w4.x; a4.y *= w4.y*w4.y; a4.z *= w4.z*w4.z; a4.w *= w4.w*w4.w;
        __syncthreads();
        As[lpart*4+0][lrow] = a4.x; As[lpart*4+1][lrow] = a4.y;
        As[lpart*4+2][lrow] = a4.z; As[lpart*4+3][lrow] = a4.w;
        Bs[lpart*4+0][lrow] = b4.x; Bs[lpart*4+1][lrow] = b4.y;
        Bs[lpart*4+2][lrow] = b4.z; Bs[lpart*4+3][lrow] = b4.w;
        __syncthreads();
#pragma unroll
        for (int kk = 0; kk < 8; kk++) {
            float4 a0 = *(const float4*)&As[kk][ty*8];
            float4 a1 = *(const float4*)&As[kk][ty*8+4];
            float4 b0 = *(const float4*)&Bs[kk][tx*8];
            float4 b1 = *(const float4*)&Bs[kk][tx*8+4];
            float av[8] = {a0.x,a0.y,a0.z,a0.w,a1.x,a1.y,a1.z,a1.w};
            float bv[8] = {b0.x,b0.y,b0.z,b0.w,b1.x,b1.y,b1.z,b1.w};
#pragma unroll
            for (int i = 0; i < 8; i++)
#pragma unroll
                for (int j = 0; j < 8; j++) acc[i][j] += av[i]*bv[j];
        }
    }
    __syncthreads();

    float npv[8], nhv[8];
#pragma unroll
    for (int i = 0; i < 8; i++) npv[i] = g_np_p[(b*LL + ty*8 + i)*NPW + k];
#pragma unroll
    for (int j = 0; j < 8; j++) nhv[j] = g_np_h[(b*LL + tx*8 + j)*NPW + k];

    float pmax[8], psum[8], qmax[8], qsum[8];
#pragma unroll
    for (int i = 0; i < 8; i++) { psum[i] = 0.f; pmax[i] = -3.0e38f; }
#pragma unroll
    for (int j = 0; j < 8; j++) { qsum[j] = 0.f; qmax[j] = -3.0e38f; }

#pragma unroll
    for (int i = 0; i < 8; i++) {
        float mp = mp_s[ty*8 + i];
#pragma unroll
        for (int j = 0; j < 8; j++) {
            float v = acc[i][j] / fmaxf(npv[i]*nhv[j], EPSV);
            psum[i] += v; qsum[j] += v;
            if (mh_s[tx*8 + j] > 0.f) pmax[i] = fmaxf(pmax[i], v);
            if (mp             > 0.f) qmax[j] = fmaxf(qmax[j], v);
        }
    }
    float lenp = g_len_p[b], lenh = g_len_h[b];

#pragma unroll
    for (int i = 0; i < 8; i++) red[ty*8+i][tx] = pmax[i];
    __syncthreads();
    if (t < 128) {
        float m = -3.0e38f;
        for (int x = 0; x < 16; x++) m = fmaxf(m, red[t][x]);
        out[(b*LL + t)*NCOL + 23 + k] = (mp_s[t] > 0.f) ? m : 0.f;
    }
    __syncthreads();
#pragma unroll
    for (int i = 0; i < 8; i++) red[ty*8+i][tx] = psum[i];
    __syncthreads();
    if (t < 128) {
        float s = 0.f;
        for (int x = 0; x < 16; x++) s += red[t][x];
        out[(b*LL + t)*NCOL + 43 + k] = (mp_s[t] > 0.f) ? s/lenh : 0.f;
    }
    __syncthreads();
#pragma unroll
    for (int j = 0; j < 8; j++) red[tx*8+j][ty] = qmax[j];
    __syncthreads();
    if (t < 128) {
        float m = -3.0e38f;
        for (int y = 0; y < 16; y++) m = fmaxf(m, red[t][y]);
        out[OUTH + (b*LL + t)*NCOL + 23 + k] = (mh_s[t] > 0.f) ? m : 0.f;
    }
    __syncthreads();
#pragma unroll
    for (int j = 0; j < 8; j++) red[tx*8+j][ty] = qsum[j];
    __syncthreads();
    if (t < 128) {
        float s = 0.f;
        for (int y = 0; y < 16; y++) s += red[t][y];
        out[OUTH + (b*LL + t)*NCOL + 43 + k] = (mh_s[t] > 0.f) ? s/lenp : 0.f;
    }
}

// ---------------- attentive: mean + max over q (p-side outputs) ----------
__global__ __launch_bounds__(256) void att_p_kernel(const float* __restrict__ mask_p,
                                                    const float* __restrict__ mask_h) {
    __shared__ float cs[8][128];
    __shared__ float mh_s[128];
    int b  = blockIdx.x >> 4;
    int p0 = (blockIdx.x & 15) * 8;
    int t  = threadIdx.x;
    if (t < 128) mh_s[t] = mask_h[b*LL + t];
    for (int idx = t; idx < 1024; idx += 256) {
        int j = idx >> 7, q = idx & 127;
        cs[j][q] = g_cos[(b*LL + p0 + j)*LL + q];
    }
    __syncthreads();
    int h = t;
    if (h < HH) {
        float sm[8], mx[8];
#pragma unroll
        for (int j = 0; j < 8; j++) { sm[j] = 0.f; mx[j] = -3.0e38f; }
        for (int q = 0; q < LL; q++) {
            if (mh_s[q] > 0.f) {
                float ch = g_chm[(b*LL + q)*HH + h];
#pragma unroll
                for (int j = 0; j < 8; j++) {
                    float v = ch * cs[j][q];
                    sm[j] += v;
                    mx[j] = fmaxf(mx[j], v);
                }
            }
        }
#pragma unroll
        for (int j = 0; j < 8; j++) {
            int p = p0 + j;
            g_amean_h[(b*LL + p)*HH + h] = sm[j] / fmaxf(g_rowsum[b*LL + p], EPSV);
            float mp = mask_p[b*LL + p];
            g_amax_h[(b*LL + p)*HH + h] = (mp > 0.f) ? mx[j] : 0.f;
        }
    }
}

// ---------------- attentive: mean + max over p (h-side outputs) ----------
__global__ __launch_bounds__(256) void att_h_kernel(const float* __restrict__ mask_p,
                                                    const float* __restrict__ mask_h) {
    __shared__ float cs[8][128];
    __shared__ float mp_s[128];
    int b  = blockIdx.x >> 4;
    int q0 = (blockIdx.x & 15) * 8;
    int t  = threadIdx.x;
    if (t < 128) mp_s[t] = mask_p[b*LL + t];
    for (int idx = t; idx < 1024; idx += 256) {
        int p = idx >> 3, j = idx & 7;
        cs[j][p] = g_cos[(b*LL + p)*LL + q0 + j];
    }
    __syncthreads();
    int h = t;
    if (h < HH) {
        float sm[8], mx[8];
#pragma unroll
        for (int j = 0; j < 8; j++) { sm[j] = 0.f; mx[j] = -3.0e38f; }
        for (int p = 0; p < LL; p++) {
            if (mp_s[p] > 0.f) {
                float cp = g_cpm[(b*LL + p)*HH + h];
#pragma unroll
                for (int j = 0; j < 8; j++) {
                    float v = cp * cs[j][p];
                    sm[j] += v;
                    mx[j] = fmaxf(mx[j], v);
                }
            }
        }
#pragma unroll
        for (int j = 0; j < 8; j++) {
            int q = q0 + j;
            g_amean_p[(b*LL + q)*HH + h] = sm[j] / fmaxf(g_colsum[b*LL + q], EPSV);
            float mh = mask_h[b*LL + q];
            g_amax_p[(b*LL + q)*HH + h] = (mh > 0.f) ? mx[j] : 0.f;
        }
    }
}

// ---------------- mpm: full / attentive / max-attentive matches ----------
// gridDim.y = side (0:p, 1:h), gridDim.z = mode (0:full, 1:att, 2:max-att)
__global__ void mpm_kernel(const float* __restrict__ w_full,
                           const float* __restrict__ w_att,
                           const float* __restrict__ w_maxatt,
                           float* __restrict__ out) {
    int side = blockIdx.y;
    int mode = blockIdx.z;
    int warp = (blockIdx.x * blockDim.x + threadIdx.x) >> 5;
    int lane = threadIdx.x & 31;
    if (warp >= BB*LL) return;
    int b = warp >> 7;

    const float* v1 = (side ? g_chm : g_cpm) + warp*HH;
    const float* v2;
    const float* w;
    int c1, cm;
    if (mode == 0) {
        w = w_full; c1 = 2; cm = 3;
        v2 = side ? (g_cpm + (b*LL + g_idx_p[b])*HH)
                  : (g_chm + (b*LL + g_idx_h[b])*HH);
    } else if (mode == 1) {
        w = w_att; c1 = 63; cm = 64;
        v2 = (side ? g_amean_p : g_amean_h) + warp*HH;
    } else {
        w = w_maxatt; c1 = 84; cm = 85;
        v2 = (side ? g_amax_p : g_amax_h) + warp*HH;
    }

    float a[7], c[7];
#pragma unroll
    for (int i = 0; i < 7; i++) {
        int h = lane + 32*i;
        a[i] = (h < HH) ? v1[h] : 0.f;
        c[i] = (h < HH) ? v2[h] : 0.f;
    }
    float s0 = 0.f, s1 = 0.f, s2 = 0.f;
#pragma unroll
    for (int i = 0; i < 7; i++) { s0 += a[i]*c[i]; s1 += a[i]*a[i]; s2 += c[i]*c[i]; }
    wred3(s0, s1, s2);
    float* ob = out + (side ? OUTH : 0) + warp*NCOL;
    if (lane == 0) ob[c1] = s0 / fmaxf(sqrtf(s1)*sqrtf(s2), EPSV);

    for (int k = 0; k < NPW; k++) {
        float t0 = 0.f, t1 = 0.f, t2 = 0.f;
#pragma unroll
        for (int i = 0; i < 7; i++) {
            int h = lane + 32*i;
            if (h < HH) {
                float wv = w[k*HH + h];
                float u = wv*wv;
                t0 += u*a[i]*c[i]; t1 += u*a[i]*a[i]; t2 += u*c[i]*c[i];
            }
        }
        wred3(t0, t1, t2);
        if (lane == 0) ob[cm + k] = t0 / fmaxf(sqrtf(t1)*sqrtf(t2), EPSV);
    }
}

// ---------------- launch ----------------
extern "C" void kernel_launch(void* const* d_in, const int* in_sizes, int n_in,
                              void* d_out, int out_size) {
    const float* ctx_p     = (const float*)d_in[0];
    const float* mask_p    = (const float*)d_in[1];
    const float* ctx_h     = (const float*)d_in[2];
    const float* mask_h    = (const float*)d_in[3];
    const float* w_full    = (const float*)d_in[4];
    const float* w_maxpool = (const float*)d_in[5];
    const float* w_att     = (const float*)d_in[6];
    const float* w_max_att = (const float*)d_in[7];
    float* out = (float*)d_out;

    lens_kernel<<<1, 64>>>(mask_p, mask_h);
    prep_kernel<<<dim3(512, 2), 256>>>(ctx_p, mask_p, ctx_h, mask_h, w_maxpool);
    cos_kernel<<<BB, 256>>>(mask_p, mask_h, out);
    maxpool_kernel<<<BB*NPW, 256>>>(w_maxpool, mask_p, mask_h, out);
    att_p_kernel<<<BB*16, 256>>>(mask_p, mask_h);
    att_h_kernel<<<BB*16, 256>>>(mask_p, mask_h);
    mpm_kernel<<<dim3(512, 2, 3), 256>>>(w_full, w_att, w_max_att, out);
}

// round 5
// speedup vs baseline: 1.2706x; 1.2706x over previous
#include <cuda_runtime.h>
#include <cuda_bf16.h>
#include <math.h>
#include <stdint.h>

#define BB   32
#define LL   128
#define HH   200
#define NPW  20
#define NCOL 105
#define EPSV 1e-8f
#define OUTH (BB*LL*NCOL)

// ---------------- scratch (device globals; no allocation allowed) ----------
__device__ float g_cpm[BB*LL*HH];
__device__ float g_chm[BB*LL*HH];
__device__ float g_norm_p[BB*LL];
__device__ float g_norm_h[BB*LL];
__device__ float g_np_p[BB*LL*NPW];
__device__ float g_np_h[BB*LL*NPW];
__device__ float g_cos[BB*LL*LL];
__device__ float g_rowsum[BB*LL];
__device__ float g_colsum[BB*LL];
__device__ float g_amean_h[BB*LL*HH];
__device__ float g_amax_h[BB*LL*HH];
__device__ float g_amean_p[BB*LL*HH];
__device__ float g_amax_p[BB*LL*HH];
__device__ float g_len_p[BB], g_len_h[BB];
__device__ int   g_idx_p[BB], g_idx_h[BB];

// ---------------- helpers ----------------
__device__ __forceinline__ float wredsum(float v) {
#pragma unroll
    for (int o = 16; o > 0; o >>= 1) v += __shfl_xor_sync(0xffffffffu, v, o);
    return v;
}
__device__ __forceinline__ void wred3(float& a, float& b, float& c) {
#pragma unroll
    for (int o = 16; o > 0; o >>= 1) {
        a += __shfl_xor_sync(0xffffffffu, a, o);
        b += __shfl_xor_sync(0xffffffffu, b, o);
        c += __shfl_xor_sync(0xffffffffu, c, o);
    }
}
__device__ __forceinline__ uint32_t smem_u32(const void* p) {
    uint32_t a;
    asm("{ .reg .u64 t; cvta.to.shared.u64 t, %1; cvt.u32.u64 %0, t; }" : "=r"(a) : "l"(p));
    return a;
}
__device__ __forceinline__ void ldm4(uint32_t* r, uint32_t addr) {
    asm volatile("ldmatrix.sync.aligned.m8n8.x4.shared.b16 {%0,%1,%2,%3}, [%4];"
                 : "=r"(r[0]), "=r"(r[1]), "=r"(r[2]), "=r"(r[3]) : "r"(addr));
}
__device__ __forceinline__ void mma16816(float* c, const uint32_t* a, const uint32_t* b) {
    asm volatile("mma.sync.aligned.m16n8k16.row.col.f32.bf16.bf16.f32 "
                 "{%0,%1,%2,%3}, {%4,%5,%6,%7}, {%8,%9}, {%0,%1,%2,%3};"
                 : "+f"(c[0]), "+f"(c[1]), "+f"(c[2]), "+f"(c[3])
                 : "r"(a[0]), "r"(a[1]), "r"(a[2]), "r"(a[3]), "r"(b[0]), "r"(b[1]));
}
__device__ __forceinline__ void split2(float x, float y, uint32_t& hp, uint32_t& lp) {
    __nv_bfloat16 hx = __float2bfloat16(x), hy = __float2bfloat16(y);
    float rx = x - __bfloat162float(hx), ry = y - __bfloat162float(hy);
    __nv_bfloat16 lx = __float2bfloat16(rx), ly = __float2bfloat16(ry);
    hp = (uint32_t)__bfloat16_as_ushort(hx) | ((uint32_t)__bfloat16_as_ushort(hy) << 16);
    lp = (uint32_t)__bfloat16_as_ushort(lx) | ((uint32_t)__bfloat16_as_ushort(ly) << 16);
}

// ---------------- mm kernel constants ----------------
#define SKT    216                   // padded K stride in elements (432B rows: 16B-aligned, conflict-free)
#define TILE_B (128*SKT*2)           // 55296 B per bf16 tile
#define OFF_A  2048
#define OFF_AL (OFF_A  + TILE_B)
#define OFF_B  (OFF_AL + TILE_B)
#define OFF_BL (OFF_B  + TILE_B)
#define SMEM_MM (OFF_BL + TILE_B)    // 223232 B dynamic smem
#define CS_STRIDE 133                // fp32 epilogue tile stride (conflict-free)

// ---------------- lens: mask sums + last-token index ----------------
__global__ void lens_kernel(const float* __restrict__ mask_p,
                            const float* __restrict__ mask_h) {
    int t = threadIdx.x;
    if (t < BB) {
        float s = 0.f;
        for (int i = 0; i < LL; i++) s += mask_p[t*LL + i];
        g_len_p[t] = s;
        int id = (int)(s + 0.5f) - 1;
        g_idx_p[t] = id < 0 ? 0 : id;
    } else if (t < 2*BB) {
        int b = t - BB;
        float s = 0.f;
        for (int i = 0; i < LL; i++) s += mask_h[b*LL + i];
        g_len_h[b] = s;
        int id = (int)(s + 0.5f) - 1;
        g_idx_h[b] = id < 0 ? 0 : id;
    }
}

// ---------------- preprocess: masked context, norms, maxpool weighted norms --
__global__ void prep_kernel(const float* __restrict__ ctx_p, const float* __restrict__ mask_p,
                            const float* __restrict__ ctx_h, const float* __restrict__ mask_h,
                            const float* __restrict__ w_mp) {
    int side = blockIdx.y;
    const float* ctx  = side ? ctx_h  : ctx_p;
    const float* mask = side ? mask_h : mask_p;
    float* xm  = side ? g_chm    : g_cpm;
    float* nrm = side ? g_norm_h : g_norm_p;
    float* npl = side ? g_np_h   : g_np_p;

    int warp = (blockIdx.x * blockDim.x + threadIdx.x) >> 5;
    int lane = threadIdx.x & 31;
    if (warp >= BB*LL) return;

    float m = mask[warp];
    const float* x = ctx + warp*HH;
    float v[7];
#pragma unroll
    for (int i = 0; i < 7; i++) {
        int h = lane + 32*i;
        float val = (h < HH) ? x[h]*m : 0.f;
        v[i] = val;
        if (h < HH) xm[warp*HH + h] = val;
    }
    float s = 0.f;
#pragma unroll
    for (int i = 0; i < 7; i++) s += v[i]*v[i];
    s = wredsum(s);
    if (lane == 0) nrm[warp] = sqrtf(s);

    for (int k = 0; k < NPW; k++) {
        float a = 0.f;
#pragma unroll
        for (int i = 0; i < 7; i++) {
            int h = lane + 32*i;
            if (h < HH) { float w = w_mp[k*HH + h]; a += w*w*v[i]*v[i]; }
        }
        a = wredsum(a);
        if (lane == 0) npl[warp*NPW + k] = sqrtf(a);
    }
}

// ---------------- unified mma.sync pairwise kernel ----------------
// grid = BB*(NPW+1); k==NPW is the unit-weight (cos) block.
// D[p,q] = sum_h w_k^2[h]*cpm[p,h]*chm[q,h], 2-term bf16 expansion:
//   D = Ah*Bh + Al*Bh + Ah*Bl  (fp32 accumulate)
__global__ __launch_bounds__(256, 1) void mm_mma_kernel(const float* __restrict__ w_mp,
                                                        float* __restrict__ out) {
    extern __shared__ char smem[];
    uint32_t sb = smem_u32(smem);
    float* nh_s = (float*)smem;   // header [0,512)

    int b = blockIdx.x / (NPW + 1);
    int k = blockIdx.x % (NPW + 1);
    int t = threadIdx.x;
    int lane = t & 31, w = t >> 5;
    bool unit = (k == NPW);

    const float* Ab = g_cpm + b*LL*HH;
    const float* Bb = g_chm + b*LL*HH;
    const float* wk = w_mp + k*HH;

    // zero-pad cols 200..207 (bytes 400..415 of each row) in all 4 tiles
    if (t < 128) {
        uint2 z = make_uint2(0u, 0u);
        int ro = t * (SKT*2);
        *(uint2*)(smem + OFF_A  + ro + 400) = z; *(uint2*)(smem + OFF_A  + ro + 408) = z;
        *(uint2*)(smem + OFF_AL + ro + 400) = z; *(uint2*)(smem + OFF_AL + ro + 408) = z;
        *(uint2*)(smem + OFF_B  + ro + 400) = z; *(uint2*)(smem + OFF_B  + ro + 408) = z;
        *(uint2*)(smem + OFF_BL + ro + 400) = z; *(uint2*)(smem + OFF_BL + ro + 408) = z;
        nh_s[t] = unit ? g_norm_h[b*LL + t] : g_np_h[(b*LL + t)*NPW + k];
    }

    // load fp32, hi/lo split to bf16, store to padded tiles
    for (int idx = t; idx < (LL*HH)/4; idx += 256) {
        int e4 = idx * 4;
        int row = e4 / HH;
        int col = e4 - row * HH;
        float4 a4 = *(const float4*)(Ab + e4);
        float4 b4 = *(const float4*)(Bb + e4);
        if (!unit) {
            float4 w4 = *(const float4*)(wk + col);
            a4.x *= w4.x*w4.x; a4.y *= w4.y*w4.y; a4.z *= w4.z*w4.z; a4.w *= w4.w*w4.w;
        }
        uint32_t h01, l01, h23, l23;
        int off = row*(SKT*2) + col*2;
        split2(a4.x, a4.y, h01, l01); split2(a4.z, a4.w, h23, l23);
        *(uint2*)(smem + OFF_A  + off) = make_uint2(h01, h23);
        *(uint2*)(smem + OFF_AL + off) = make_uint2(l01, l23);
        split2(b4.x, b4.y, h01, l01); split2(b4.z, b4.w, h23, l23);
        *(uint2*)(smem + OFF_B  + off) = make_uint2(h01, h23);
        *(uint2*)(smem + OFF_BL + off) = make_uint2(l01, l23);
    }
    __syncthreads();

    // -------- warp tiles: warp w -> rows (w&3)*32.., cols (w>>2)*64.. --------
    int mrow0 = (w & 3) * 32;
    int n0    = (w >> 2) * 64;

    uint32_t adA[2], adAl[2], adB[4], adBl[4];
    {
        int r = lane & 7, half = (lane >> 3) & 1, ksel = lane >> 4;
#pragma unroll
        for (int mi = 0; mi < 2; mi++) {
            int row = mrow0 + mi*16 + half*8 + r;
            uint32_t byo = (uint32_t)(row*(SKT*2) + ksel*16);
            adA[mi]  = sb + OFF_A  + byo;
            adAl[mi] = sb + OFF_AL + byo;
        }
        int sel = lane >> 3;
        int kb2 = (sel & 1) * 16;
        int rb  = (sel >> 1) * 8 + (lane & 7);
#pragma unroll
        for (int ng = 0; ng < 4; ng++) {
            int row = n0 + ng*16 + rb;
            uint32_t byo = (uint32_t)(row*(SKT*2) + kb2);
            adB[ng]  = sb + OFF_B  + byo;
            adBl[ng] = sb + OFF_BL + byo;
        }
    }

    float acc[2][8][4];
#pragma unroll
    for (int mi = 0; mi < 2; mi++)
#pragma unroll
        for (int nt = 0; nt < 8; nt++)
#pragma unroll
            for (int e = 0; e < 4; e++) acc[mi][nt][e] = 0.f;

    for (int ks = 0; ks < 13; ks++) {
        uint32_t kb = (uint32_t)ks * 32;   // 16 bf16 = 32 bytes
        uint32_t ah[2][4], al_[2][4], bh[4][4], bl[4][4];
#pragma unroll
        for (int mi = 0; mi < 2; mi++) { ldm4(ah[mi], adA[mi] + kb); ldm4(al_[mi], adAl[mi] + kb); }
#pragma unroll
        for (int ng = 0; ng < 4; ng++) { ldm4(bh[ng], adB[ng] + kb); ldm4(bl[ng], adBl[ng] + kb); }
#pragma unroll
        for (int mi = 0; mi < 2; mi++)
#pragma unroll
            for (int nt = 0; nt < 8; nt++)
                mma16816(acc[mi][nt], ah[mi],  &bh[nt>>1][(nt&1)*2]);
#pragma unroll
        for (int mi = 0; mi < 2; mi++)
#pragma unroll
            for (int nt = 0; nt < 8; nt++)
                mma16816(acc[mi][nt], al_[mi], &bh[nt>>1][(nt&1)*2]);
#pragma unroll
        for (int mi = 0; mi < 2; mi++)
#pragma unroll
            for (int nt = 0; nt < 8; nt++)
                mma16816(acc[mi][nt], ah[mi],  &bl[nt>>1][(nt&1)*2]);
    }
    __syncthreads();   // tiles dead; cs overwrites OFF_A region

    // -------- epilogue: normalize into padded fp32 tile --------
    float lenp_f = g_len_p[b], lenh_f = g_len_h[b];
    int lenp_i = (int)(lenp_f + 0.5f), lenh_i = (int)(lenh_f + 0.5f);
    float* cs = (float*)(smem + OFF_A);

    float np4[4];
#pragma unroll
    for (int mi = 0; mi < 2; mi++)
#pragma unroll
        for (int half = 0; half < 2; half++) {
            int row = mrow0 + mi*16 + half*8 + (lane >> 2);
            np4[mi*2+half] = unit ? g_norm_p[b*LL + row]
                                  : g_np_p[(b*LL + row)*NPW + k];
        }
    float nh0[8], nh1[8];
#pragma unroll
    for (int nt = 0; nt < 8; nt++) {
        int c = n0 + nt*8 + (lane & 3)*2;
        nh0[nt] = nh_s[c]; nh1[nt] = nh_s[c+1];
    }
#pragma unroll
    for (int mi = 0; mi < 2; mi++)
#pragma unroll
        for (int half = 0; half < 2; half++) {
            int row = mrow0 + mi*16 + half*8 + (lane >> 2);
            float np = np4[mi*2+half];
#pragma unroll
            for (int nt = 0; nt < 8; nt++) {
                int c = n0 + nt*8 + (lane & 3)*2;
                float v0 = acc[mi][nt][half*2+0] / fmaxf(np*nh0[nt], EPSV);
                float v1 = acc[mi][nt][half*2+1] / fmaxf(np*nh1[nt], EPSV);
                cs[row*CS_STRIDE + c]     = v0;
                cs[row*CS_STRIDE + c + 1] = v1;
            }
        }
    __syncthreads();

    // -------- masked row/col reductions --------
    if (t < 128) {
        int p = t;
        float rmax = -3.0e38f, rsum = 0.f;
        for (int q = 0; q < 128; q++) {
            float v = cs[p*CS_STRIDE + q];
            rsum += v;
            if (q < lenh_i) rmax = fmaxf(rmax, v);
        }
        bool pv = p < lenp_i;
        float* ob = out + (b*LL + p)*NCOL;
        if (unit) {
            ob[0] = pv ? rmax : 0.f;
            ob[1] = pv ? rsum/lenh_f : 0.f;
            g_rowsum[b*LL + p] = rsum;
        } else {
            ob[23 + k] = pv ? rmax : 0.f;
            ob[43 + k] = pv ? rsum/lenh_f : 0.f;
        }

        int q = t;
        float cmax = -3.0e38f, csum = 0.f;
        for (int pp = 0; pp < 128; pp++) {
            float v = cs[pp*CS_STRIDE + q];
            csum += v;
            if (pp < lenp_i) cmax = fmaxf(cmax, v);
        }
        bool qv = q < lenh_i;
        float* ob2 = out + OUTH + (b*LL + q)*NCOL;
        if (unit) {
            ob2[0] = qv ? cmax : 0.f;
            ob2[1] = qv ? csum/lenp_f : 0.f;
            g_colsum[b*LL + q] = csum;
            for (int r = 0; r < 128; r++)
                g_cos[(b*LL + r)*LL + q] = cs[r*CS_STRIDE + q];
        } else {
            ob2[23 + k] = qv ? cmax : 0.f;
            ob2[43 + k] = qv ? csum/lenp_f : 0.f;
        }
    }
}

// ---------------- attentive: mean + max over q (p-side outputs) ----------
__global__ __launch_bounds__(256) void att_p_kernel(const float* __restrict__ mask_p,
                                                    const float* __restrict__ mask_h) {
    __shared__ float cs[8][128];
    __shared__ float mh_s[128];
    int b  = blockIdx.x >> 4;
    int p0 = (blockIdx.x & 15) * 8;
    int t  = threadIdx.x;
    if (t < 128) mh_s[t] = mask_h[b*LL + t];
    for (int idx = t; idx < 1024; idx += 256) {
        int j = idx >> 7, q = idx & 127;
        cs[j][q] = g_cos[(b*LL + p0 + j)*LL + q];
    }
    __syncthreads();
    int h = t;
    if (h < HH) {
        float sm[8], mx[8];
#pragma unroll
        for (int j = 0; j < 8; j++) { sm[j] = 0.f; mx[j] = -3.0e38f; }
        for (int q = 0; q < LL; q++) {
            if (mh_s[q] > 0.f) {
                float ch = g_chm[(b*LL + q)*HH + h];
#pragma unroll
                for (int j = 0; j < 8; j++) {
                    float v = ch * cs[j][q];
                    sm[j] += v;
                    mx[j] = fmaxf(mx[j], v);
                }
            }
        }
#pragma unroll
        for (int j = 0; j < 8; j++) {
            int p = p0 + j;
            g_amean_h[(b*LL + p)*HH + h] = sm[j] / fmaxf(g_rowsum[b*LL + p], EPSV);
            float mp = mask_p[b*LL + p];
            g_amax_h[(b*LL + p)*HH + h] = (mp > 0.f) ? mx[j] : 0.f;
        }
    }
}

// ---------------- attentive: mean + max over p (h-side outputs) ----------
__global__ __launch_bounds__(256) void att_h_kernel(const float* __restrict__ mask_p,
                                                    const float* __restrict__ mask_h) {
    __shared__ float cs[8][128];
    __shared__ float mp_s[128];
    int b  = blockIdx.x >> 4;
    int q0 = (blockIdx.x & 15) * 8;
    int t  = threadIdx.x;
    if (t < 128) mp_s[t] = mask_p[b*LL + t];
    for (int idx = t; idx < 1024; idx += 256) {
        int p = idx >> 3, j = idx & 7;
        cs[j][p] = g_cos[(b*LL + p)*LL + q0 + j];
    }
    __syncthreads();
    int h = t;
    if (h < HH) {
        float sm[8], mx[8];
#pragma unroll
        for (int j = 0; j < 8; j++) { sm[j] = 0.f; mx[j] = -3.0e38f; }
        for (int p = 0; p < LL; p++) {
            if (mp_s[p] > 0.f) {
                float cp = g_cpm[(b*LL + p)*HH + h];
#pragma unroll
                for (int j = 0; j < 8; j++) {
                    float v = cp * cs[j][p];
                    sm[j] += v;
                    mx[j] = fmaxf(mx[j], v);
                }
            }
        }
#pragma unroll
        for (int j = 0; j < 8; j++) {
            int q = q0 + j;
            g_amean_p[(b*LL + q)*HH + h] = sm[j] / fmaxf(g_colsum[b*LL + q], EPSV);
            float mh = mask_h[b*LL + q];
            g_amax_p[(b*LL + q)*HH + h] = (mh > 0.f) ? mx[j] : 0.f;
        }
    }
}

// ---------------- mpm: full / attentive / max-attentive matches ----------
__global__ void mpm_kernel(const float* __restrict__ w_full,
                           const float* __restrict__ w_att,
                           const float* __restrict__ w_maxatt,
                           float* __restrict__ out) {
    int side = blockIdx.y;
    int mode = blockIdx.z;
    int warp = (blockIdx.x * blockDim.x + threadIdx.x) >> 5;
    int lane = threadIdx.x & 31;
    if (warp >= BB*LL) return;
    int b = warp >> 7;

    const float* v1 = (side ? g_chm : g_cpm) + warp*HH;
    const float* v2;
    const float* w;
    int c1, cm;
    if (mode == 0) {
        w = w_full; c1 = 2; cm = 3;
        v2 = side ? (g_cpm + (b*LL + g_idx_p[b])*HH)
                  : (g_chm + (b*LL + g_idx_h[b])*HH);
    } else if (mode == 1) {
        w = w_att; c1 = 63; cm = 64;
        v2 = (side ? g_amean_p : g_amean_h) + warp*HH;
    } else {
        w = w_maxatt; c1 = 84; cm = 85;
        v2 = (side ? g_amax_p : g_amax_h) + warp*HH;
    }

    float a[7], c[7];
#pragma unroll
    for (int i = 0; i < 7; i++) {
        int h = lane + 32*i;
        a[i] = (h < HH) ? v1[h] : 0.f;
        c[i] = (h < HH) ? v2[h] : 0.f;
    }
    float s0 = 0.f, s1 = 0.f, s2 = 0.f;
#pragma unroll
    for (int i = 0; i < 7; i++) { s0 += a[i]*c[i]; s1 += a[i]*a[i]; s2 += c[i]*c[i]; }
    wred3(s0, s1, s2);
    float* ob = out + (side ? OUTH : 0) + warp*NCOL;
    if (lane == 0) ob[c1] = s0 / fmaxf(sqrtf(s1)*sqrtf(s2), EPSV);

    for (int k = 0; k < NPW; k++) {
        float t0 = 0.f, t1 = 0.f, t2 = 0.f;
#pragma unroll
        for (int i = 0; i < 7; i++) {
            int h = lane + 32*i;
            if (h < HH) {
                float wv = w[k*HH + h];
                float u = wv*wv;
                t0 += u*a[i]*c[i]; t1 += u*a[i]*a[i]; t2 += u*c[i]*c[i];
            }
        }
        wred3(t0, t1, t2);
        if (lane == 0) ob[cm + k] = t0 / fmaxf(sqrtf(t1)*sqrtf(t2), EPSV);
    }
}

// ---------------- launch ----------------
extern "C" void kernel_launch(void* const* d_in, const int* in_sizes, int n_in,
                              void* d_out, int out_size) {
    const float* ctx_p     = (const float*)d_in[0];
    const float* mask_p    = (const float*)d_in[1];
    const float* ctx_h     = (const float*)d_in[2];
    const float* mask_h    = (const float*)d_in[3];
    const float* w_full    = (const float*)d_in[4];
    const float* w_maxpool = (const float*)d_in[5];
    const float* w_att     = (const float*)d_in[6];
    const float* w_max_att = (const float*)d_in[7];
    float* out = (float*)d_out;

    cudaFuncSetAttribute(mm_mma_kernel, cudaFuncAttributeMaxDynamicSharedMemorySize, SMEM_MM);

    lens_kernel<<<1, 64>>>(mask_p, mask_h);
    prep_kernel<<<dim3(512, 2), 256>>>(ctx_p, mask_p, ctx_h, mask_h, w_maxpool);
    mm_mma_kernel<<<BB*(NPW+1), 256, SMEM_MM>>>(w_maxpool, out);
    att_p_kernel<<<BB*16, 256>>>(mask_p, mask_h);
    att_h_kernel<<<BB*16, 256>>>(mask_p, mask_h);
    mpm_kernel<<<dim3(512, 2, 3), 256>>>(w_full, w_att, w_max_att, out);
}